// round 17
// baseline (speedup 1.0000x reference)
#include <cuda_runtime.h>
#include <stdint.h>

// Problem constants (fixed by the reference)
#define BB 4
#define LL 4096
#define VV 8192
#define NPOS (BB * LL)          // 16384 positions

// Gather tile shape: TJ j-cols x TV v-rows (smem = TJ*TV*4 = 64 KB)
#define TJ 32
#define TV 512
#define NJB (VV / TJ)           // 256 buckets (by idx >> 5)
#define NVT (VV / TV)           // 16 v-tiles
#define NTILES (NJB * NVT)      // 4096 tiles
#define CAP 256                 // per-bucket capacity (mean 64, sd ~8)

// Scratch (no cudaMalloc allowed)
__device__ int   g_bcount[NJB];
__device__ int   g_bpos[NJB][CAP];      // packed: (pos << 5) | (idx & 31)
__device__ float g_add[BB][VV];         // 0.01*sigma[b]*rowsum(W)[v] + bias[v]

// Grid-wide barrier state (zero-init at load; reset by last block each run)
__device__ unsigned g_arrive;
__device__ int      g_go;
__device__ unsigned g_done;

// ---------------------------------------------------------------------------
// Fused persistent kernel. Grid is clamped to fully-resident capacity by the
// host (occupancy query), so the grid-wide barrier cannot deadlock.
//
// Phase 1 (overlapped across blocks):
//   blocks [0, 256):  colsum — 32 warps/block, one warp per W row,
//                     rows [bid*32, bid*32+32) -> g_add.
//   blocks [256, G):  buckets — each block owns buckets jb = bid-256,
//                     bid-256+(G-256), ...: detect int64-vs-int32 (int64 LE
//                     with values < 8192 => every odd 32-bit word is zero),
//                     compact matching positions via a shared counter.
//   (If G <= 256: colsum blocks also grid-stride the buckets afterwards.)
// Barrier: arrive counter + go flag (atomics, L2). Release ordering via
//   __threadfence before arrive / after spin.
// Phase 2: tile loop t = bid, bid+G, ... over 4096 tiles; body identical to
//   the round-16 gather (XOR-swizzled transpose, warp-per-position epilogue,
//   2 KB contiguous writes, anchor prefetch, plain stores).
// Exit: done counter; last block resets barrier state (graph-replay safe).
// ---------------------------------------------------------------------------
__global__ void __launch_bounds__(1024, 2)
fused_kernel(const int* __restrict__ idx_words,
             const float* __restrict__ Wm,
             const float* __restrict__ sigma,
             const float* __restrict__ bias,
             float* __restrict__ out) {
    extern __shared__ float smf[];           // TJ*TV floats = 64 KB (phase 2)
    const int G    = gridDim.x;
    const int bid  = blockIdx.x;
    const int tid  = threadIdx.x;            // 1024 threads
    const int lane = tid & 31;
    const int warp = tid >> 5;               // 0..31

    // ====================== Phase 1 ======================
    if (bid < 256) {
        // ---- colsum: rows [bid*32, bid*32+32), one warp per row ----
        int row = bid * 32 + warp;
        const float4* rp = (const float4*)(Wm + (size_t)row * VV);
        float s = 0.0f;
#pragma unroll 4
        for (int i = lane; i < VV / 4; i += 32) {
            float4 v = rp[i];
            s += (v.x + v.y) + (v.z + v.w);
        }
#pragma unroll
        for (int o = 16; o; o >>= 1) s += __shfl_xor_sync(0xffffffffu, s, o);
        if (lane < BB) {
            g_add[lane][row] = 0.01f * sigma[lane] * s + bias[row];
        }
    }

    // ---- bucket assignment ----
    int bstart, bstride;
    if (G > 256) { bstart = (bid >= 256) ? bid - 256 : -1; bstride = G - 256; }
    else         { bstart = bid;                           bstride = G; }

    if (bstart >= 0 && bstart < NJB) {
        // dtype detection (odd 32-bit words all zero <=> int64 LE, vals<8192)
        int bad = 0;
        for (int k = tid; k < NPOS; k += 1024) {
            if ((k & 1) && idx_words[k] != 0) bad = 1;
        }
        bad = __syncthreads_or(bad);
        const int is64 = !bad;

        __shared__ int cnt;
        for (int jb = bstart; jb < NJB; jb += bstride) {
            if (tid == 0) cnt = 0;
            __syncthreads();
            for (int pos = tid; pos < NPOS; pos += 1024) {
                int idx = is64 ? idx_words[2 * pos]   // low word of LE int64
                               : idx_words[pos];
                idx = max(0, min(VV - 1, idx));       // reference clamps
                if ((idx >> 5) == jb) {
                    int s = atomicAdd(&cnt, 1);
                    if (s < CAP) g_bpos[jb][s] = (pos << 5) | (idx & 31);
                }
            }
            __syncthreads();
            if (tid == 0) g_bcount[jb] = min(cnt, CAP);
            __syncthreads();
        }
    }

    // ====================== Grid barrier ======================
    __syncthreads();
    if (tid == 0) {
        __threadfence();                          // publish phase-1 writes
        unsigned old = atomicAdd(&g_arrive, 1u);
        if (old == (unsigned)G - 1u) {
            atomicExch(&g_go, 1);                 // release
        }
        while (atomicAdd(&g_go, 0) == 0) { }      // acquire spin (L2 atomics)
        __threadfence();
    }
    __syncthreads();

    // ====================== Phase 2: gather tiles ======================
    const float4* gaddv = (const float4*)g_add;   // [BB * VV/4]

    for (int t = bid; t < NTILES; t += G) {
        const int vt = t & (NVT - 1);             // 0..15
        const int jb = t >> 4;                    // 0..255
        const int v0 = vt * TV;
        const int j0 = jb * TJ;

        // --- load + swizzled transpose: 512 rows x 8 float4 ---
        const float4* Wp = (const float4*)(Wm + (size_t)v0 * VV + j0);
#pragma unroll
        for (int it = 0; it < (TV * (TJ / 4)) / 1024; it++) {
            int i  = tid + it * 1024;
            int r  = i >> 3;                      // v-row 0..511
            int c4 = i & 7;                       // float4-col 0..7
            float4 val = Wp[(size_t)r * (VV / 4) + c4];
            int base = 4 * ((r >> 2) ^ c4) + (r & 3);
            smf[(4 * c4 + 0) * TV + base] = val.x;
            smf[(4 * c4 + 1) * TV + base] = val.y;
            smf[(4 * c4 + 2) * TV + base] = val.z;
            smf[(4 * c4 + 3) * TV + base] = val.w;
        }
        __syncthreads();

        // --- epilogue: one warp per position, 4x512B = 2 KB per position ---
        const int count = g_bcount[jb];
        const float4* smv = (const float4*)smf;
        const int gb = (v0 >> 2) + lane;          // f4 index in g_add row
        float* outp = out + (size_t)v0 + 4 * lane;
        const int* __restrict__ bp = g_bpos[jb];

        if (warp < count) {
            int pk = bp[warp];                    // prefetch first anchor
            for (int p = warp; p < count; p += 32) {
                int pn = (p + 32 < count) ? bp[p + 32] : 0;
                int pos = pk >> 5;
                int jl  = pk & 31;
                int b   = pos >> 12;              // LL = 4096
                const float4* smrow = smv + jl * 128 + (lane ^ (jl >> 2));
                const float4* ga    = gaddv + b * (VV / 4) + gb;
                float* o = outp + (size_t)pos * VV;
#pragma unroll
                for (int c = 0; c < 4; c++) {
                    float4 w = smrow[32 * c];     // conflict-free LDS.128
                    float4 a = ga[32 * c];        // L1/L2-hot
                    float4 r4 = make_float4(w.x + a.x, w.y + a.y,
                                            w.z + a.z, w.w + a.w);
                    *(float4*)(o + 128 * c) = r4; // 2 KB contiguous
                }
                pk = pn;
            }
        }
        __syncthreads();                          // smem reuse for next tile
    }

    // ====================== Reset barrier state ======================
    __syncthreads();
    if (tid == 0) {
        unsigned old = atomicAdd(&g_done, 1u);
        if (old == (unsigned)G - 1u) {            // last block cleans up
            g_arrive = 0;
            atomicExch(&g_go, 0);
            __threadfence();
            atomicExch(&g_done, 0u);
        }
    }
}

// ---------------------------------------------------------------------------
// Inputs per metadata order: indices[B,L] (int64 or int32), sigma[B] f32,
// W[V,V] f32, bias[V] f32. Output: float32 [B,L,V].
// ---------------------------------------------------------------------------
extern "C" void kernel_launch(void* const* d_in, const int* in_sizes, int n_in,
                              void* d_out, int out_size) {
    const int*   idx   = (const int*)d_in[0];
    const float* sigma = (const float*)d_in[1];
    const float* Wm    = (const float*)d_in[2];
    const float* bias  = (const float*)d_in[3];
    float* out = (float*)d_out;

    const int smem = TJ * TV * (int)sizeof(float);   // 65536 B dynamic
    cudaFuncSetAttribute(fused_kernel,
                         cudaFuncAttributeMaxDynamicSharedMemorySize, smem);

    // Grid = fully-resident capacity (barrier is deadlock-free by construction)
    int dev = 0, nsm = 148, maxb = 2;
    cudaGetDevice(&dev);
    cudaDeviceGetAttribute(&nsm, cudaDevAttrMultiProcessorCount, dev);
    cudaOccupancyMaxActiveBlocksPerMultiprocessor(&maxb, fused_kernel,
                                                  1024, smem);
    if (maxb < 1) maxb = 1;
    int grid = nsm * maxb;
    if (grid > NTILES) grid = NTILES;

    fused_kernel<<<grid, 1024, smem>>>(idx, Wm, sigma, bias, out);
}